// round 14
// baseline (speedup 1.0000x reference)
#include <cuda_runtime.h>
#include <cuda_bf16.h>
#include <cuda_fp16.h>
#include <math.h>
#include <stdint.h>

#define D_MODEL 1024
#define NHEAD 16
#define HEAD_DIM 64
#define BATCH 2
#define SEQ 2048
#define MTOT (BATCH * SEQ) /* 4096 */
#define DD (D_MODEL * D_MODEL)
#define NBITS_WORDS (3 * MTOT * D_MODEL / 32)   /* 393216 */

// ---------------------------------------------------------------------------
// Scratch (device globals — no allocation allowed anywhere)
// ---------------------------------------------------------------------------
__device__ __half g_xhlf[MTOT * D_MODEL];
__device__ __half g_whlf[3 * DD];
__device__ __half g_wo[DD];
__device__ __half g_qh[MTOT * D_MODEL];
__device__ __half g_kh[MTOT * D_MODEL];
__device__ __half g_vh[MTOT * D_MODEL];
__device__ __half g_aat[MTOT * D_MODEL];
__device__ uint32_t g_flagbits[NBITS_WORDS];

// ---------------------------------------------------------------------------
// helpers
// ---------------------------------------------------------------------------
__device__ __forceinline__ uint32_t smem_u32(const void* p) {
    uint32_t a;
    asm("{ .reg .u64 t; cvta.to.shared.u64 t, %1; cvt.u32.u64 %0, t; }" : "=r"(a) : "l"(p));
    return a;
}
__device__ __forceinline__ void cp_async16(uint32_t sa, const void* ga) {
    asm volatile("cp.async.cg.shared.global [%0], [%1], 16;" :: "r"(sa), "l"(ga) : "memory");
}
#define CP_COMMIT() asm volatile("cp.async.commit_group;" ::: "memory")
#define CP_WAIT2()  asm volatile("cp.async.wait_group 2;" ::: "memory")

__device__ __forceinline__ void ldm_x4(uint32_t& r0, uint32_t& r1, uint32_t& r2, uint32_t& r3,
                                       uint32_t addr) {
    asm volatile("ldmatrix.sync.aligned.m8n8.x4.shared.b16 {%0,%1,%2,%3}, [%4];"
                 : "=r"(r0), "=r"(r1), "=r"(r2), "=r"(r3) : "r"(addr));
}
__device__ __forceinline__ void ldm_x4t(uint32_t& r0, uint32_t& r1, uint32_t& r2, uint32_t& r3,
                                        uint32_t addr) {
    asm volatile("ldmatrix.sync.aligned.m8n8.x4.trans.shared.b16 {%0,%1,%2,%3}, [%4];"
                 : "=r"(r0), "=r"(r1), "=r"(r2), "=r"(r3) : "r"(addr));
}
__device__ __forceinline__ void mma_f16(float* c, const uint32_t* a, const uint32_t* b) {
    asm volatile(
        "mma.sync.aligned.m16n8k16.row.col.f32.f16.f16.f32 "
        "{%0,%1,%2,%3}, {%4,%5,%6,%7}, {%8,%9}, {%0,%1,%2,%3};"
        : "+f"(c[0]), "+f"(c[1]), "+f"(c[2]), "+f"(c[3])
        : "r"(a[0]), "r"(a[1]), "r"(a[2]), "r"(a[3]), "r"(b[0]), "r"(b[1]));
}

// ---------------------------------------------------------------------------
// small kernels
// ---------------------------------------------------------------------------
__device__ __forceinline__ uint2 cvt_quad(float4 x) {
    __half2 a = __floats2half2_rn(x.x, x.y);
    __half2 b = __floats2half2_rn(x.z, x.w);
    uint2 o;
    o.x = *(uint32_t*)&a;
    o.y = *(uint32_t*)&b;
    return o;
}

// fused: fp32->fp16 conversion for x/Wq/Wk/Wv/Wo AND flag-bitmap zeroing
__global__ void conv_all(const float4* __restrict__ x,
                         const float4* __restrict__ wq, const float4* __restrict__ wk,
                         const float4* __restrict__ wv, const float4* __restrict__ wo,
                         uint2* __restrict__ xh, uint2* __restrict__ whlf,
                         uint2* __restrict__ woh, uint32_t* __restrict__ bits,
                         int nx4, int nw4)
{
    int i = blockIdx.x * blockDim.x + threadIdx.x;
    if (i < NBITS_WORDS) bits[i] = 0;
    if (i < nx4) { xh[i] = cvt_quad(x[i]); return; }
    i -= nx4;
    if (i < nw4) { whlf[i] = cvt_quad(wq[i]); return; }
    i -= nw4;
    if (i < nw4) { whlf[nw4 + i] = cvt_quad(wk[i]); return; }
    i -= nw4;
    if (i < nw4) { whlf[2 * nw4 + i] = cvt_quad(wv[i]); return; }
    i -= nw4;
    if (i < nw4) woh[i] = cvt_quad(wo[i]);
}

// ---------------------------------------------------------------------------
// QKV GEMM: fp16 mma (1 product), BK=32, 4-stage cp.async pipeline with
// EARLY load issue (load before compute). SFN epilogue + bitmap flagging.
// ---------------------------------------------------------------------------
#define BM 128
#define BN 128
#define BK 32
#define ROWB 80
#define HMATB (128 * ROWB)              /* 10240 */
#define HSTAGEB (2 * HMATB)             /* 20480 per stage */
#define NSTAGE 4
#define HGEMM_SMEM (NSTAGE * HSTAGEB)   /* 81920 -> 2 blocks/SM on 228KB */
#define SFN_THR 4.0e-3f

__global__ __launch_bounds__(256, 2) void gemm_hsfn(
    const __half* __restrict__ Ah, const __half* __restrict__ WhB,
    const float* __restrict__ bq, const float* __restrict__ bk, const float* __restrict__ bv,
    __half* __restrict__ Cq, __half* __restrict__ Ck, __half* __restrict__ Cv,
    uint32_t* __restrict__ bits)
{
    extern __shared__ char dsm[];
    const uint32_t sb = smem_u32(dsm);

    const int z = blockIdx.z;
    const __half* Wh = WhB + (size_t)z * DD;
    const float* bias = (z == 0) ? bq : (z == 1) ? bk : bv;
    __half* C = (z == 0) ? Cq : (z == 1) ? Ck : Cv;

    const int tid = threadIdx.x;
    const int wid = tid >> 5;
    const int lane = tid & 31;
    const int wm = wid >> 2;
    const int wn = wid & 3;
    const int bm = blockIdx.y * BM;
    const int bn = blockIdx.x * BN;

    const __half* mats[2] = {Ah, Wh};

    auto load_stage = [&](int sg, int kt) {
        const int kbase = kt * BK;
#pragma unroll
        for (int i = 0; i < 4; i++) {
            int idx = tid + i * 256;
            int mat = idx >> 9;
            int w = idx & 511;
            int row = w >> 2;
            int c = w & 3;
            int grow = (mat ? bn : bm) + row;
            const __half* gp = mats[mat] + (size_t)grow * D_MODEL + kbase + c * 8;
            uint32_t sa = sb + sg * HSTAGEB + mat * HMATB + row * ROWB + c * 16;
            cp_async16(sa, gp);
        }
    };

    float acc[4][4][4];
#pragma unroll
    for (int a = 0; a < 4; a++)
#pragma unroll
        for (int b2 = 0; b2 < 4; b2++)
#pragma unroll
            for (int q = 0; q < 4; q++) acc[a][b2][q] = 0.f;

    load_stage(0, 0); CP_COMMIT();
    load_stage(1, 1); CP_COMMIT();
    load_stage(2, 2); CP_COMMIT();

    const int lr = lane & 7;
    const int l3 = (lane >> 3) & 1;
    const int l4 = (lane >> 4) & 1;

    const int NK = D_MODEL / BK;         // 32
    for (int kt = 0; kt < NK; kt++) {
        const int sg = kt & (NSTAGE - 1);
        CP_WAIT2();                       // stage kt resident
        __syncthreads();                  // all warps done reading stage kt-1

        // EARLY: issue next tile's loads into the stage freed by kt-1
        if (kt + 3 < NK) load_stage((kt + 3) & (NSTAGE - 1), kt + 3);
        CP_COMMIT();

        const uint32_t abase = sb + sg * HSTAGEB + (wm * 64) * ROWB;
        const uint32_t wbase = sb + sg * HSTAGEB + HMATB + (wn * 32) * ROWB;

#pragma unroll
        for (int ks = 0; ks < 2; ks++) {
            uint32_t af[4][4];
            uint32_t bf_[4][2];
#pragma unroll
            for (int mt = 0; mt < 4; mt++) {
                uint32_t addr = abase + (mt * 16 + lr + l3 * 8) * ROWB + ks * 32 + l4 * 16;
                ldm_x4(af[mt][0], af[mt][1], af[mt][2], af[mt][3], addr);
            }
#pragma unroll
            for (int pr = 0; pr < 2; pr++) {
                uint32_t r0, r1, r2, r3;
                uint32_t addr = wbase + (pr * 16 + lr + l4 * 8) * ROWB + ks * 32 + l3 * 16;
                ldm_x4(r0, r1, r2, r3, addr);
                bf_[pr * 2 + 0][0] = r0;  bf_[pr * 2 + 0][1] = r1;
                bf_[pr * 2 + 1][0] = r2;  bf_[pr * 2 + 1][1] = r3;
            }
#pragma unroll
            for (int mt = 0; mt < 4; mt++)
#pragma unroll
                for (int nt = 0; nt < 4; nt++)
                    mma_f16(acc[mt][nt], af[mt], bf_[nt]);
        }
        // no trailing sync: top-of-loop sync covers read-retire before reuse
    }

    const int qrow = lane >> 2;
    const int qcol = (lane & 3) * 2;
    const size_t zbase = (size_t)z * MTOT * D_MODEL;
#pragma unroll
    for (int mt = 0; mt < 4; mt++) {
#pragma unroll
        for (int nt = 0; nt < 4; nt++) {
            const int col = bn + wn * 32 + nt * 8 + qcol;
            const float b0 = bias[col], b1 = bias[col + 1];
#pragma unroll
            for (int half_ = 0; half_ < 2; half_++) {
                const int row = bm + wm * 64 + mt * 16 + qrow + half_ * 8;
                float v0 = acc[mt][nt][half_ * 2 + 0] + b0;
                float v1 = acc[mt][nt][half_ * 2 + 1] + b1;
                float t0 = v0 * 2.0f, t1 = v1 * 2.0f;
                float r0 = rintf(t0), r1 = rintf(t1);
                if (fabsf(t0 - r0) > 0.5f - SFN_THR) {
                    size_t g = zbase + (size_t)row * D_MODEL + col;
                    atomicOr(&bits[g >> 5], 1u << (g & 31));
                }
                if (fabsf(t1 - r1) > 0.5f - SFN_THR) {
                    size_t g = zbase + (size_t)row * D_MODEL + col + 1;
                    atomicOr(&bits[g >> 5], 1u << (g & 31));
                }
                r0 = fminf(8.f, fmaxf(-8.f, r0));
                r1 = fminf(8.f, fmaxf(-8.f, r1));
                __half2 o = __floats2half2_rn(r0 * 0.5f, r1 * 0.5f);
                *(__half2*)(C + (size_t)row * D_MODEL + col) = o;
            }
        }
    }
}

// ---------------------------------------------------------------------------
// Fix-up: recompute flagged elements with fp32 dot (warp per element)
// ---------------------------------------------------------------------------
__global__ __launch_bounds__(256) void fixup_kernel(
    const float* __restrict__ x,
    const float* __restrict__ Wq, const float* __restrict__ Wk, const float* __restrict__ Wv,
    const float* __restrict__ bq, const float* __restrict__ bk, const float* __restrict__ bv,
    __half* __restrict__ Q, __half* __restrict__ K, __half* __restrict__ V,
    const uint32_t* __restrict__ bits)
{
    const int warp = (blockIdx.x * blockDim.x + threadIdx.x) >> 5;
    const int lane = threadIdx.x & 31;
    const int nw = (gridDim.x * blockDim.x) >> 5;

    for (int w = warp; w < NBITS_WORDS; w += nw) {
        uint32_t word = bits[w];
        while (word) {
            int bit = __ffs(word) - 1;
            word &= word - 1;
            size_t g = ((size_t)w << 5) + bit;
            int z = (int)(g / ((size_t)MTOT * D_MODEL));
            size_t rem = g - (size_t)z * MTOT * D_MODEL;
            int row = (int)(rem >> 10);
            int col = (int)(rem & 1023);
            const float* W = (z == 0) ? Wq : (z == 1) ? Wk : Wv;
            const float* bias = (z == 0) ? bq : (z == 1) ? bk : bv;
            __half* C = (z == 0) ? Q : (z == 1) ? K : V;

            const float* xr = x + (size_t)row * D_MODEL;
            const float* wr = W + (size_t)col * D_MODEL;
            float4 av[8], bv_[8];
#pragma unroll
            for (int u = 0; u < 8; u++) {
                av[u]  = *(const float4*)(xr + lane * 4 + u * 128);
                bv_[u] = *(const float4*)(wr + lane * 4 + u * 128);
            }
            float s = 0.f;
#pragma unroll
            for (int u = 0; u < 8; u++) {
                s = fmaf(av[u].x, bv_[u].x, s); s = fmaf(av[u].y, bv_[u].y, s);
                s = fmaf(av[u].z, bv_[u].z, s); s = fmaf(av[u].w, bv_[u].w, s);
            }
#pragma unroll
            for (int o = 16; o; o >>= 1) s += __shfl_xor_sync(0xffffffffu, s, o);
            if (lane == 0) {
                float c = s + bias[col];
                float r = fminf(8.f, fmaxf(-8.f, rintf(c * 2.f)));
                C[(size_t)row * D_MODEL + col] = __float2half(r * 0.5f);
            }
        }
    }
}

// ---------------------------------------------------------------------------
// Flash attention: pure fp16 mma (1 product QK^T and PV), fused qk-norm.
// ---------------------------------------------------------------------------
#define AT_ROWB 144
#define FA_SMEM (128 * AT_ROWB)   /* 18432 */

__global__ __launch_bounds__(256, 1) void flash_mma(
    const __half* __restrict__ Qg, const __half* __restrict__ Kg,
    const __half* __restrict__ Vg,
    const float* __restrict__ gq, const float* __restrict__ gk,
    __half* __restrict__ Og)
{
    extern __shared__ char smp[];
    const uint32_t sb = smem_u32(smp);
    const int oQ = 0, oK = 0, oV = 64 * AT_ROWB;

    const int tid = threadIdx.x, wid = tid >> 5, lane = tid & 31;
    const int b = blockIdx.y >> 4, h = blockIdx.y & 15;
    const int q0 = blockIdx.x * 128;

    const int lr = lane & 7, l3 = (lane >> 3) & 1, l4 = (lane >> 4) & 1;

    {
        const int row = tid >> 1;
        const int cb = (tid & 1) * 32;
        const __half* qp = Qg + ((size_t)(b * SEQ + q0 + row)) * D_MODEL + h * HEAD_DIM + cb;
        float v[32];
        const uint4* qp4 = (const uint4*)qp;
#pragma unroll
        for (int u = 0; u < 4; u++) {
            uint4 raw = qp4[u];
            const __half2* hp = (const __half2*)&raw;
#pragma unroll
            for (int j = 0; j < 4; j++) {
                float2 f = __half22float2(hp[j]);
                v[u * 8 + j * 2] = f.x;  v[u * 8 + j * 2 + 1] = f.y;
            }
        }
        float ss = 0.f;
#pragma unroll
        for (int i = 0; i < 32; i++) ss = fmaf(v[i], v[i], ss);
        ss += __shfl_xor_sync(0xffffffffu, ss, 1);
        const float inv = rsqrtf(ss * (1.0f / 64.0f) + 1e-6f) * 0.125f;

        char* dq = smp + oQ + row * AT_ROWB + cb * 2;
#pragma unroll
        for (int t = 0; t < 16; t++) {
            float a = v[t * 2]     * inv * __ldg(gq + cb + t * 2);
            float c = v[t * 2 + 1] * inv * __ldg(gq + cb + t * 2 + 1);
            *(__half2*)(dq + t * 4) = __floats2half2_rn(a, c);
        }
    }
    __syncthreads();

    uint32_t qf[4][4];
    {
        const int rbase = wid * 16 + lr + l3 * 8;
#pragma unroll
        for (int ks = 0; ks < 4; ks++)
            ldm_x4(qf[ks][0], qf[ks][1], qf[ks][2], qf[ks][3],
                   sb + oQ + rbase * AT_ROWB + ks * 32 + l4 * 16);
    }
    __syncthreads();

    float m_lo = -INFINITY, m_hi = -INFINITY, l_lo = 0.f, l_hi = 0.f;
    float acc[8][4];
#pragma unroll
    for (int i = 0; i < 8; i++)
#pragma unroll
        for (int j = 0; j < 4; j++) acc[i][j] = 0.f;

    for (int kt = 0; kt < SEQ / 64; kt++) {
        {
            const int row = tid >> 2;
            const int cb = (tid & 3) * 16;
            const __half* kp = Kg + ((size_t)(b * SEQ + kt * 64 + row)) * D_MODEL + h * HEAD_DIM + cb;
            const __half* vp = Vg + ((size_t)(b * SEQ + kt * 64 + row)) * D_MODEL + h * HEAD_DIM + cb;
            float kv[16];
            const uint4* kp4 = (const uint4*)kp;
            const uint4* vp4 = (const uint4*)vp;
            char* dk = smp + oK + row * AT_ROWB + cb * 2;
            char* dv = smp + oV + row * AT_ROWB + cb * 2;
#pragma unroll
            for (int u = 0; u < 2; u++) {
                uint4 kr = kp4[u];
                *(uint4*)(dv + u * 16) = vp4[u];
                const __half2* khp = (const __half2*)&kr;
#pragma unroll
                for (int j = 0; j < 4; j++) {
                    float2 kf = __half22float2(khp[j]);
                    kv[u * 8 + j * 2] = kf.x;  kv[u * 8 + j * 2 + 1] = kf.y;
                }
            }
            float ss = 0.f;
#pragma unroll
            for (int i = 0; i < 16; i++) ss = fmaf(kv[i], kv[i], ss);
            ss += __shfl_xor_sync(0xffffffffu, ss, 1);
            ss += __shfl_xor_sync(0xffffffffu, ss, 2);
            const float inv = rsqrtf(ss * (1.0f / 64.0f) + 1e-6f);
#pragma unroll
            for (int t = 0; t < 8; t++) {
                float a = kv[t * 2]     * inv * __ldg(gk + cb + t * 2);
                float c = kv[t * 2 + 1] * inv * __ldg(gk + cb + t * 2 + 1);
                *(__half2*)(dk + t * 4) = __floats2half2_rn(a, c);
            }
        }
        __syncthreads();

        float s[8][4];
#pragma unroll
        for (int i = 0; i < 8; i++)
#pragma unroll
            for (int j = 0; j < 4; j++) s[i][j] = 0.f;

#pragma unroll
        for (int np = 0; np < 4; np++) {
            const int rb = np * 16 + lr + l4 * 8;
#pragma unroll
            for (int ks = 0; ks < 4; ks++) {
                uint32_t k0, k1, k2, k3;
                ldm_x4(k0, k1, k2, k3, sb + oK + rb * AT_ROWB + ks * 32 + l3 * 16);
                uint32_t b0[2] = {k0, k1}, b1[2] = {k2, k3};
                mma_f16(s[np * 2 + 0], qf[ks], b0);
                mma_f16(s[np * 2 + 1], qf[ks], b1);
            }
        }

        float mx_lo = m_lo, mx_hi = m_hi;
#pragma unroll
        for (int i = 0; i < 8; i++) {
            mx_lo = fmaxf(mx_lo, fmaxf(s[i][0], s[i][1]));
            mx_hi = fmaxf(mx_hi, fmaxf(s[i][2], s[i][3]));
        }
        mx_lo = fmaxf(mx_lo, __shfl_xor_sync(0xffffffffu, mx_lo, 1));
        mx_lo = fmaxf(mx_lo, __shfl_xor_sync(0xffffffffu, mx_lo, 2));
        mx_hi = fmaxf(mx_hi, __shfl_xor_sync(0xffffffffu, mx_hi, 1));
        mx_hi = fmaxf(mx_hi, __shfl_xor_sync(0xffffffffu, mx_hi, 2));

        const float corr_lo = __expf(m_lo - mx_lo);
        const float corr_hi = __expf(m_hi - mx_hi);
        m_lo = mx_lo; m_hi = mx_hi;
        l_lo *= corr_lo; l_hi *= corr_hi;
#pragma unroll
        for (int i = 0; i < 8; i++) {
            acc[i][0] *= corr_lo; acc[i][1] *= corr_lo;
            acc[i][2] *= corr_hi; acc[i][3] *= corr_hi;
        }

        uint32_t ph[4][4];
#pragma unroll
        for (int t = 0; t < 4; t++) {
#pragma unroll
            for (int half_ = 0; half_ < 2; half_++) {
                const int nt = 2 * t + half_;
                float p0 = __expf(s[nt][0] - mx_lo);
                float p1 = __expf(s[nt][1] - mx_lo);
                float p2 = __expf(s[nt][2] - mx_hi);
                float p3 = __expf(s[nt][3] - mx_hi);
                l_lo += p0 + p1; l_hi += p2 + p3;
                __half2 h01 = __floats2half2_rn(p0, p1);
                __half2 h23 = __floats2half2_rn(p2, p3);
                ph[t][half_ * 2 + 0] = *(uint32_t*)&h01;
                ph[t][half_ * 2 + 1] = *(uint32_t*)&h23;
            }
        }

#pragma unroll
        for (int np = 0; np < 4; np++) {
#pragma unroll
            for (int t = 0; t < 4; t++) {
                uint32_t v0, v1, v2, v3;
                ldm_x4t(v0, v1, v2, v3,
                        sb + oV + (t * 16 + lr + l3 * 8) * AT_ROWB + np * 32 + l4 * 16);
                uint32_t b0[2] = {v0, v1}, b1[2] = {v2, v3};
                mma_f16(acc[np * 2 + 0], ph[t], b0);
                mma_f16(acc[np * 2 + 1], ph[t], b1);
            }
        }
        __syncthreads();
    }

    l_lo += __shfl_xor_sync(0xffffffffu, l_lo, 1);
    l_lo += __shfl_xor_sync(0xffffffffu, l_lo, 2);
    l_hi += __shfl_xor_sync(0xffffffffu, l_hi, 1);
    l_hi += __shfl_xor_sync(0xffffffffu, l_hi, 2);
    const float inv_lo = 1.0f / l_lo;
    const float inv_hi = 1.0f / l_hi;

    const int r_lo = q0 + wid * 16 + (lane >> 2);
    const int r_hi = r_lo + 8;
    const size_t base_lo = ((size_t)(b * SEQ + r_lo)) * D_MODEL + h * HEAD_DIM + (lane & 3) * 2;
    const size_t base_hi = ((size_t)(b * SEQ + r_hi)) * D_MODEL + h * HEAD_DIM + (lane & 3) * 2;
#pragma unroll
    for (int nt = 0; nt < 8; nt++) {
        *(__half2*)(Og + base_lo + nt * 8) = __floats2half2_rn(acc[nt][0] * inv_lo, acc[nt][1] * inv_lo);
        *(__half2*)(Og + base_hi + nt * 8) = __floats2half2_rn(acc[nt][2] * inv_hi, acc[nt][3] * inv_hi);
    }
}

// ---------------------------------------------------------------------------
// Wo GEMM: fp16 mma (1 product), BK=32, 4-stage early-issue pipeline.
// ---------------------------------------------------------------------------
__global__ __launch_bounds__(256, 2) void gemm_out(
    const __half* __restrict__ Ah, const __half* __restrict__ Wh,
    const float* __restrict__ bias, float* __restrict__ C)
{
    extern __shared__ char dsm[];
    const uint32_t sb = smem_u32(dsm);

    const int tid = threadIdx.x;
    const int wid = tid >> 5;
    const int lane = tid & 31;
    const int wm = wid >> 2;
    const int wn = wid & 3;
    const int bm = blockIdx.y * BM;
    const int bn = blockIdx.x * BN;

    const __half* mats[2] = {Ah, Wh};

    auto load_stage = [&](int sg, int kt) {
        const int kbase = kt * BK;
#pragma unroll
        for (int i = 0; i < 4; i++) {
            int idx = tid + i * 256;
            int mat = idx >> 9;
            int w = idx & 511;
            int row = w >> 2;
            int c = w & 3;
            int grow = (mat ? bn : bm) + row;
            const __half* gp = mats[mat] + (size_t)grow * D_MODEL + kbase + c * 8;
            uint32_t sa = sb + sg * HSTAGEB + mat * HMATB + row * ROWB + c * 16;
            cp_async16(sa, gp);
        }
    };

    float acc[4][4][4];
#pragma unroll
    for (int a = 0; a < 4; a++)
#pragma unroll
        for (int b2 = 0; b2 < 4; b2++)
#pragma unroll
            for (int q = 0; q < 4; q++) acc[a][b2][q] = 0.f;

    load_stage(0, 0); CP_COMMIT();
    load_stage(1, 1); CP_COMMIT();
    load_stage(2, 2); CP_COMMIT();

    const int lr = lane & 7;
    const int l3 = (lane >> 3) & 1;
    const int l4 = (lane >> 4) & 1;

    const int NK = D_MODEL / BK;
    for (int kt = 0; kt < NK; kt++) {
        const int sg = kt & (NSTAGE - 1);
        CP_WAIT2();
        __syncthreads();

        if (kt + 3 < NK) load_stage((kt + 3) & (NSTAGE - 1), kt + 3);
        CP_COMMIT();

        const uint32_t abase = sb + sg * HSTAGEB + (wm * 64) * ROWB;
        const uint32_t wbase = sb + sg * HSTAGEB + HMATB + (wn * 32) * ROWB;

#pragma unroll
        for (int ks = 0; ks < 2; ks++) {
            uint32_t af[4][4];
            uint32_t bf_[4][2];
#pragma unroll
            for (int mt = 0; mt < 4; mt++) {
                uint32_t addr = abase + (mt * 16 + lr + l3 * 8) * ROWB + ks * 32 + l4 * 16;
                ldm_x4(af[mt][0], af[mt][1], af[mt][2], af[mt][3], addr);
            }
#pragma unroll
            for (int pr = 0; pr < 2; pr++) {
                uint32_t r0, r1, r2, r3;
                uint32_t addr = wbase + (pr * 16 + lr + l4 * 8) * ROWB + ks * 32 + l3 * 16;
                ldm_x4(r0, r1, r2, r3, addr);
                bf_[pr * 2 + 0][0] = r0;  bf_[pr * 2 + 0][1] = r1;
                bf_[pr * 2 + 1][0] = r2;  bf_[pr * 2 + 1][1] = r3;
            }
#pragma unroll
            for (int mt = 0; mt < 4; mt++)
#pragma unroll
                for (int nt = 0; nt < 4; nt++)
                    mma_f16(acc[mt][nt], af[mt], bf_[nt]);
        }
    }

    const int qrow = lane >> 2;
    const int qcol = (lane & 3) * 2;
#pragma unroll
    for (int mt = 0; mt < 4; mt++) {
#pragma unroll
        for (int nt = 0; nt < 4; nt++) {
            const int col = bn + wn * 32 + nt * 8 + qcol;
            const float b0 = bias[col], b1 = bias[col + 1];
#pragma unroll
            for (int half_ = 0; half_ < 2; half_++) {
                const int row = bm + wm * 64 + mt * 16 + qrow + half_ * 8;
                float v0 = acc[mt][nt][half_ * 2 + 0] + b0;
                float v1 = acc[mt][nt][half_ * 2 + 1] + b1;
                *(float2*)(C + (size_t)row * D_MODEL + col) = make_float2(v0, v1);
            }
        }
    }
}

// ---------------------------------------------------------------------------
// Launcher
// ---------------------------------------------------------------------------
extern "C" void kernel_launch(void* const* d_in, const int* in_sizes, int n_in,
                              void* d_out, int out_size)
{
    (void)in_sizes; (void)n_in; (void)out_size;
    const float* x  = (const float*)d_in[0];
    const float* Wq = (const float*)d_in[1];
    const float* bq = (const float*)d_in[2];
    const float* Wk = (const float*)d_in[3];
    const float* bk = (const float*)d_in[4];
    const float* Wv = (const float*)d_in[5];
    const float* bv = (const float*)d_in[6];
    const float* Wo = (const float*)d_in[7];
    const float* bo = (const float*)d_in[8];
    const float* gq = (const float*)d_in[9];
    const float* gk = (const float*)d_in[10];
    float* out = (float*)d_out;

    __half *xhlf, *whlf, *wo, *qh, *kh, *vh, *aat;
    uint32_t* bits;
    cudaGetSymbolAddress((void**)&xhlf, g_xhlf);
    cudaGetSymbolAddress((void**)&whlf, g_whlf);
    cudaGetSymbolAddress((void**)&wo, g_wo);
    cudaGetSymbolAddress((void**)&qh, g_qh);
    cudaGetSymbolAddress((void**)&kh, g_kh);
    cudaGetSymbolAddress((void**)&vh, g_vh);
    cudaGetSymbolAddress((void**)&aat, g_aat);
    cudaGetSymbolAddress((void**)&bits, g_flagbits);

    cudaFuncSetAttribute(gemm_hsfn, cudaFuncAttributeMaxDynamicSharedMemorySize, HGEMM_SMEM);
    cudaFuncSetAttribute(gemm_out, cudaFuncAttributeMaxDynamicSharedMemorySize, HGEMM_SMEM);
    cudaFuncSetAttribute(flash_mma, cudaFuncAttributeMaxDynamicSharedMemorySize, FA_SMEM);

    const int nx4 = MTOT * D_MODEL / 4;
    const int nw4 = DD / 4;
    const int ntot = nx4 + 4 * nw4;   // >= NBITS_WORDS (393216 <= 5242880)

    conv_all<<<(ntot + 255) / 256, 256>>>((const float4*)x, (const float4*)Wq,
                                          (const float4*)Wk, (const float4*)Wv,
                                          (const float4*)Wo, (uint2*)xhlf,
                                          (uint2*)whlf, (uint2*)wo, bits, nx4, nw4);

    {
        dim3 ggrid(D_MODEL / BN, MTOT / BM, 3);
        gemm_hsfn<<<ggrid, 256, HGEMM_SMEM>>>(xhlf, whlf, bq, bk, bv, qh, kh, vh, bits);
    }

    fixup_kernel<<<4096, 256>>>(x, Wq, Wk, Wv, bq, bk, bv, qh, kh, vh, bits);

    {
        dim3 fgrid(SEQ / 128, BATCH * NHEAD);
        flash_mma<<<fgrid, 256, FA_SMEM>>>(qh, kh, vh, gq, gk, aat);
    }

    {
        dim3 mgrid(D_MODEL / BN, MTOT / BM);
        gemm_out<<<mgrid, 256, HGEMM_SMEM>>>(aat, wo, bo, out);
    }
}

// round 15
// speedup vs baseline: 1.2699x; 1.2699x over previous
#include <cuda_runtime.h>
#include <cuda_bf16.h>
#include <cuda_fp16.h>
#include <math.h>
#include <stdint.h>

#define D_MODEL 1024
#define NHEAD 16
#define HEAD_DIM 64
#define BATCH 2
#define SEQ 2048
#define MTOT (BATCH * SEQ) /* 4096 */
#define DD (D_MODEL * D_MODEL)
#define NBITS_WORDS (3 * MTOT * D_MODEL / 32)   /* 393216 */

// ---------------------------------------------------------------------------
// Scratch (device globals — no allocation allowed anywhere)
// ---------------------------------------------------------------------------
__device__ __half g_xhlf[MTOT * D_MODEL];
__device__ __half g_whlf[3 * DD];
__device__ __half g_wo[DD];
__device__ __half g_qh[MTOT * D_MODEL];
__device__ __half g_kh[MTOT * D_MODEL];
__device__ __half g_vh[MTOT * D_MODEL];
__device__ __half g_aat[MTOT * D_MODEL];
__device__ uint32_t g_flagbits[NBITS_WORDS];

// ---------------------------------------------------------------------------
// helpers
// ---------------------------------------------------------------------------
__device__ __forceinline__ uint32_t smem_u32(const void* p) {
    uint32_t a;
    asm("{ .reg .u64 t; cvta.to.shared.u64 t, %1; cvt.u32.u64 %0, t; }" : "=r"(a) : "l"(p));
    return a;
}
__device__ __forceinline__ void cp_async16(uint32_t sa, const void* ga) {
    asm volatile("cp.async.cg.shared.global [%0], [%1], 16;" :: "r"(sa), "l"(ga) : "memory");
}
#define CP_COMMIT() asm volatile("cp.async.commit_group;" ::: "memory")
#define CP_WAIT1()  asm volatile("cp.async.wait_group 1;" ::: "memory")
#define CP_WAIT2()  asm volatile("cp.async.wait_group 2;" ::: "memory")

__device__ __forceinline__ void ldm_x4(uint32_t& r0, uint32_t& r1, uint32_t& r2, uint32_t& r3,
                                       uint32_t addr) {
    asm volatile("ldmatrix.sync.aligned.m8n8.x4.shared.b16 {%0,%1,%2,%3}, [%4];"
                 : "=r"(r0), "=r"(r1), "=r"(r2), "=r"(r3) : "r"(addr));
}
__device__ __forceinline__ void ldm_x4t(uint32_t& r0, uint32_t& r1, uint32_t& r2, uint32_t& r3,
                                        uint32_t addr) {
    asm volatile("ldmatrix.sync.aligned.m8n8.x4.trans.shared.b16 {%0,%1,%2,%3}, [%4];"
                 : "=r"(r0), "=r"(r1), "=r"(r2), "=r"(r3) : "r"(addr));
}
__device__ __forceinline__ void mma_f16(float* c, const uint32_t* a, const uint32_t* b) {
    asm volatile(
        "mma.sync.aligned.m16n8k16.row.col.f32.f16.f16.f32 "
        "{%0,%1,%2,%3}, {%4,%5,%6,%7}, {%8,%9}, {%0,%1,%2,%3};"
        : "+f"(c[0]), "+f"(c[1]), "+f"(c[2]), "+f"(c[3])
        : "r"(a[0]), "r"(a[1]), "r"(a[2]), "r"(a[3]), "r"(b[0]), "r"(b[1]));
}

// ---------------------------------------------------------------------------
// small kernels
// ---------------------------------------------------------------------------
__device__ __forceinline__ uint2 cvt_quad(float4 x) {
    __half2 a = __floats2half2_rn(x.x, x.y);
    __half2 b = __floats2half2_rn(x.z, x.w);
    uint2 o;
    o.x = *(uint32_t*)&a;
    o.y = *(uint32_t*)&b;
    return o;
}

__global__ void conv_all(const float4* __restrict__ x,
                         const float4* __restrict__ wq, const float4* __restrict__ wk,
                         const float4* __restrict__ wv, const float4* __restrict__ wo,
                         uint2* __restrict__ xh, uint2* __restrict__ whlf,
                         uint2* __restrict__ woh, uint32_t* __restrict__ bits,
                         int nx4, int nw4)
{
    int i = blockIdx.x * blockDim.x + threadIdx.x;
    if (i < NBITS_WORDS) bits[i] = 0;
    if (i < nx4) { xh[i] = cvt_quad(x[i]); return; }
    i -= nx4;
    if (i < nw4) { whlf[i] = cvt_quad(wq[i]); return; }
    i -= nw4;
    if (i < nw4) { whlf[nw4 + i] = cvt_quad(wk[i]); return; }
    i -= nw4;
    if (i < nw4) { whlf[2 * nw4 + i] = cvt_quad(wv[i]); return; }
    i -= nw4;
    if (i < nw4) woh[i] = cvt_quad(wo[i]);
}

// ---------------------------------------------------------------------------
// qk-norm on fp16, in place: Q <- (Q/rms)*gq*0.125, K <- (K/rms)*gk
// warp per row (64 halves); Q and K handled together.
// ---------------------------------------------------------------------------
__global__ void qknorm_h(__half2* __restrict__ Q, __half2* __restrict__ K,
                         const float* __restrict__ gq, const float* __restrict__ gk)
{
    const int row = blockIdx.x * blockDim.y + threadIdx.y;
    const int lane = threadIdx.x;

    __half2* qb = Q + (size_t)row * 32;
    __half2* kb = K + (size_t)row * 32;

    float2 xq = __half22float2(qb[lane]);
    float2 xk = __half22float2(kb[lane]);

    float sq = xq.x * xq.x + xq.y * xq.y;
    float sk = xk.x * xk.x + xk.y * xk.y;
#pragma unroll
    for (int o = 16; o; o >>= 1) {
        sq += __shfl_xor_sync(0xffffffffu, sq, o);
        sk += __shfl_xor_sync(0xffffffffu, sk, o);
    }
    const float invq = rsqrtf(sq * (1.0f / 64.0f) + 1e-6f) * 0.125f;
    const float invk = rsqrtf(sk * (1.0f / 64.0f) + 1e-6f);

    const float gq0 = __ldg(gq + lane * 2), gq1 = __ldg(gq + lane * 2 + 1);
    const float gk0 = __ldg(gk + lane * 2), gk1 = __ldg(gk + lane * 2 + 1);

    qb[lane] = __floats2half2_rn(xq.x * invq * gq0, xq.y * invq * gq1);
    kb[lane] = __floats2half2_rn(xk.x * invk * gk0, xk.y * invk * gk1);
}

// ---------------------------------------------------------------------------
// QKV GEMM: fp16 mma (1 product), BK=64, 2-stage pipeline (round-13 best).
// ---------------------------------------------------------------------------
#define BM 128
#define BN 128
#define BK 64
#define ROWB 144
#define HMATB (128 * ROWB)              /* 18432 */
#define HSTAGEB (2 * HMATB)             /* 36864 */
#define NSTAGE 2
#define HGEMM_SMEM (NSTAGE * HSTAGEB)   /* 73728 */
#define SFN_THR 4.0e-3f

__global__ __launch_bounds__(256, 2) void gemm_hsfn(
    const __half* __restrict__ Ah, const __half* __restrict__ WhB,
    const float* __restrict__ bq, const float* __restrict__ bk, const float* __restrict__ bv,
    __half* __restrict__ Cq, __half* __restrict__ Ck, __half* __restrict__ Cv,
    uint32_t* __restrict__ bits)
{
    extern __shared__ char dsm[];
    const uint32_t sb = smem_u32(dsm);

    const int z = blockIdx.z;
    const __half* Wh = WhB + (size_t)z * DD;
    const float* bias = (z == 0) ? bq : (z == 1) ? bk : bv;
    __half* C = (z == 0) ? Cq : (z == 1) ? Ck : Cv;

    const int tid = threadIdx.x;
    const int wid = tid >> 5;
    const int lane = tid & 31;
    const int wm = wid >> 2;
    const int wn = wid & 3;
    const int bm = blockIdx.y * BM;
    const int bn = blockIdx.x * BN;

    const __half* mats[2] = {Ah, Wh};

    auto load_stage = [&](int sg, int kt) {
        const int kbase = kt * BK;
#pragma unroll
        for (int i = 0; i < 8; i++) {
            int idx = tid + i * 256;
            int mat = idx >> 10;
            int w = idx & 1023;
            int row = w >> 3;
            int c = w & 7;
            int grow = (mat ? bn : bm) + row;
            const __half* gp = mats[mat] + (size_t)grow * D_MODEL + kbase + c * 8;
            uint32_t sa = sb + sg * HSTAGEB + mat * HMATB + row * ROWB + c * 16;
            cp_async16(sa, gp);
        }
    };

    float acc[4][4][4];
#pragma unroll
    for (int a = 0; a < 4; a++)
#pragma unroll
        for (int b2 = 0; b2 < 4; b2++)
#pragma unroll
            for (int q = 0; q < 4; q++) acc[a][b2][q] = 0.f;

    load_stage(0, 0); CP_COMMIT();
    load_stage(1, 1); CP_COMMIT();

    const int lr = lane & 7;
    const int l3 = (lane >> 3) & 1;
    const int l4 = (lane >> 4) & 1;

    const int NK = D_MODEL / BK;        // 16
    for (int kt = 0; kt < NK; kt++) {
        const int sg = kt & 1;
        CP_WAIT1();
        __syncthreads();

        const uint32_t abase = sb + sg * HSTAGEB + (wm * 64) * ROWB;
        const uint32_t wbase = sb + sg * HSTAGEB + HMATB + (wn * 32) * ROWB;

#pragma unroll
        for (int ks = 0; ks < 4; ks++) {
            uint32_t af[4][4];
            uint32_t bf_[4][2];
#pragma unroll
            for (int mt = 0; mt < 4; mt++) {
                uint32_t addr = abase + (mt * 16 + lr + l3 * 8) * ROWB + ks * 32 + l4 * 16;
                ldm_x4(af[mt][0], af[mt][1], af[mt][2], af[mt][3], addr);
            }
#pragma unroll
            for (int pr = 0; pr < 2; pr++) {
                uint32_t r0, r1, r2, r3;
                uint32_t addr = wbase + (pr * 16 + lr + l4 * 8) * ROWB + ks * 32 + l3 * 16;
                ldm_x4(r0, r1, r2, r3, addr);
                bf_[pr * 2 + 0][0] = r0;  bf_[pr * 2 + 0][1] = r1;
                bf_[pr * 2 + 1][0] = r2;  bf_[pr * 2 + 1][1] = r3;
            }
#pragma unroll
            for (int mt = 0; mt < 4; mt++)
#pragma unroll
                for (int nt = 0; nt < 4; nt++)
                    mma_f16(acc[mt][nt], af[mt], bf_[nt]);
        }
        __syncthreads();
        if (kt + NSTAGE < NK) load_stage(sg, kt + NSTAGE);
        CP_COMMIT();
    }

    const int qrow = lane >> 2;
    const int qcol = (lane & 3) * 2;
    const size_t zbase = (size_t)z * MTOT * D_MODEL;
#pragma unroll
    for (int mt = 0; mt < 4; mt++) {
#pragma unroll
        for (int nt = 0; nt < 4; nt++) {
            const int col = bn + wn * 32 + nt * 8 + qcol;
            const float b0 = bias[col], b1 = bias[col + 1];
#pragma unroll
            for (int half_ = 0; half_ < 2; half_++) {
                const int row = bm + wm * 64 + mt * 16 + qrow + half_ * 8;
                float v0 = acc[mt][nt][half_ * 2 + 0] + b0;
                float v1 = acc[mt][nt][half_ * 2 + 1] + b1;
                float t0 = v0 * 2.0f, t1 = v1 * 2.0f;
                float r0 = rintf(t0), r1 = rintf(t1);
                if (fabsf(t0 - r0) > 0.5f - SFN_THR) {
                    size_t g = zbase + (size_t)row * D_MODEL + col;
                    atomicOr(&bits[g >> 5], 1u << (g & 31));
                }
                if (fabsf(t1 - r1) > 0.5f - SFN_THR) {
                    size_t g = zbase + (size_t)row * D_MODEL + col + 1;
                    atomicOr(&bits[g >> 5], 1u << (g & 31));
                }
                r0 = fminf(8.f, fmaxf(-8.f, r0));
                r1 = fminf(8.f, fmaxf(-8.f, r1));
                __half2 o = __floats2half2_rn(r0 * 0.5f, r1 * 0.5f);
                *(__half2*)(C + (size_t)row * D_MODEL + col) = o;
            }
        }
    }
}

// ---------------------------------------------------------------------------
// Fix-up: recompute flagged elements with fp32 dot (warp per element)
// ---------------------------------------------------------------------------
__global__ __launch_bounds__(256) void fixup_kernel(
    const float* __restrict__ x,
    const float* __restrict__ Wq, const float* __restrict__ Wk, const float* __restrict__ Wv,
    const float* __restrict__ bq, const float* __restrict__ bk, const float* __restrict__ bv,
    __half* __restrict__ Q, __half* __restrict__ K, __half* __restrict__ V,
    const uint32_t* __restrict__ bits)
{
    const int warp = (blockIdx.x * blockDim.x + threadIdx.x) >> 5;
    const int lane = threadIdx.x & 31;
    const int nw = (gridDim.x * blockDim.x) >> 5;

    for (int w = warp; w < NBITS_WORDS; w += nw) {
        uint32_t word = bits[w];
        while (word) {
            int bit = __ffs(word) - 1;
            word &= word - 1;
            size_t g = ((size_t)w << 5) + bit;
            int z = (int)(g / ((size_t)MTOT * D_MODEL));
            size_t rem = g - (size_t)z * MTOT * D_MODEL;
            int row = (int)(rem >> 10);
            int col = (int)(rem & 1023);
            const float* W = (z == 0) ? Wq : (z == 1) ? Wk : Wv;
            const float* bias = (z == 0) ? bq : (z == 1) ? bk : bv;
            __half* C = (z == 0) ? Q : (z == 1) ? K : V;

            const float* xr = x + (size_t)row * D_MODEL;
            const float* wr = W + (size_t)col * D_MODEL;
            float4 av[8], bv_[8];
#pragma unroll
            for (int u = 0; u < 8; u++) {
                av[u]  = *(const float4*)(xr + lane * 4 + u * 128);
                bv_[u] = *(const float4*)(wr + lane * 4 + u * 128);
            }
            float s = 0.f;
#pragma unroll
            for (int u = 0; u < 8; u++) {
                s = fmaf(av[u].x, bv_[u].x, s); s = fmaf(av[u].y, bv_[u].y, s);
                s = fmaf(av[u].z, bv_[u].z, s); s = fmaf(av[u].w, bv_[u].w, s);
            }
#pragma unroll
            for (int o = 16; o; o >>= 1) s += __shfl_xor_sync(0xffffffffu, s, o);
            if (lane == 0) {
                float c = s + bias[col];
                float r = fminf(8.f, fmaxf(-8.f, rintf(c * 2.f)));
                C[(size_t)row * D_MODEL + col] = __float2half(r * 0.5f);
            }
        }
    }
}

// ---------------------------------------------------------------------------
// Flash attention v2: inputs pre-normalized fp16; K/V staged via 4-stage
// cp.async pipeline with early issue; Q staged once via cp.async.
// ---------------------------------------------------------------------------
#define AT_ROWB 144
#define KMATB (64 * AT_ROWB)            /* 9216 */
#define KVSTG (2 * KMATB)               /* 18432 per stage (K + V) */
#define FA_NST 4
#define FA_SMEM (128 * AT_ROWB + FA_NST * KVSTG)  /* 18432 + 73728 = 92160 */

__global__ __launch_bounds__(256) void flash_mma(
    const __half* __restrict__ Qg, const __half* __restrict__ Kg,
    const __half* __restrict__ Vg, __half* __restrict__ Og)
{
    extern __shared__ char smp[];
    const uint32_t sb = smem_u32(smp);
    const uint32_t oKV = 128 * AT_ROWB;

    const int tid = threadIdx.x, wid = tid >> 5, lane = tid & 31;
    const int b = blockIdx.y >> 4, h = blockIdx.y & 15;
    const int q0 = blockIdx.x * 128;

    const int lr = lane & 7, l3 = (lane >> 3) & 1, l4 = (lane >> 4) & 1;

    auto load_q = [&]() {
#pragma unroll
        for (int i = 0; i < 4; i++) {
            int idx = tid + i * 256;            // 128 rows x 8 chunks
            int row = idx >> 3, c = idx & 7;
            const __half* gp = Qg + ((size_t)(b * SEQ + q0 + row)) * D_MODEL + h * HEAD_DIM + c * 8;
            cp_async16(sb + row * AT_ROWB + c * 16, gp);
        }
    };
    auto load_kv = [&](int sg, int kt) {
#pragma unroll
        for (int i = 0; i < 4; i++) {
            int idx = tid + i * 256;            // 2 mats x 64 rows x 8 chunks
            int mat = idx >> 9;
            int w = idx & 511;
            int row = w >> 3, c = w & 7;
            const __half* gp = (mat ? Vg : Kg) +
                ((size_t)(b * SEQ + kt * 64 + row)) * D_MODEL + h * HEAD_DIM + c * 8;
            cp_async16(sb + oKV + sg * KVSTG + mat * KMATB + row * AT_ROWB + c * 16, gp);
        }
    };

    load_q(); load_kv(0, 0); CP_COMMIT();
    load_kv(1, 1); CP_COMMIT();
    load_kv(2, 2); CP_COMMIT();

    CP_WAIT2();                 // group 0 (Q + KV0) complete
    __syncthreads();

    uint32_t qf[4][4];
    {
        const int rbase = wid * 16 + lr + l3 * 8;
#pragma unroll
        for (int ks = 0; ks < 4; ks++)
            ldm_x4(qf[ks][0], qf[ks][1], qf[ks][2], qf[ks][3],
                   sb + rbase * AT_ROWB + ks * 32 + l4 * 16);
    }

    float m_lo = -INFINITY, m_hi = -INFINITY, l_lo = 0.f, l_hi = 0.f;
    float acc[8][4];
#pragma unroll
    for (int i = 0; i < 8; i++)
#pragma unroll
        for (int j = 0; j < 4; j++) acc[i][j] = 0.f;

    const int NT = SEQ / 64;    // 32
    for (int kt = 0; kt < NT; kt++) {
        if (kt > 0) {
            CP_WAIT2();          // KV kt resident
            __syncthreads();     // all warps done with stage kt-1
        }
        if (kt + 3 < NT) load_kv((kt + 3) & (FA_NST - 1), kt + 3);
        CP_COMMIT();

        const uint32_t kb_ = sb + oKV + (kt & (FA_NST - 1)) * KVSTG;
        const uint32_t vb_ = kb_ + KMATB;

        float s[8][4];
#pragma unroll
        for (int i = 0; i < 8; i++)
#pragma unroll
            for (int j = 0; j < 4; j++) s[i][j] = 0.f;

#pragma unroll
        for (int np = 0; np < 4; np++) {
            const int rb = np * 16 + lr + l4 * 8;
#pragma unroll
            for (int ks = 0; ks < 4; ks++) {
                uint32_t k0, k1, k2, k3;
                ldm_x4(k0, k1, k2, k3, kb_ + rb * AT_ROWB + ks * 32 + l3 * 16);
                uint32_t b0[2] = {k0, k1}, b1[2] = {k2, k3};
                mma_f16(s[np * 2 + 0], qf[ks], b0);
                mma_f16(s[np * 2 + 1], qf[ks], b1);
            }
        }

        float mx_lo = m_lo, mx_hi = m_hi;
#pragma unroll
        for (int i = 0; i < 8; i++) {
            mx_lo = fmaxf(mx_lo, fmaxf(s[i][0], s[i][1]));
            mx_hi = fmaxf(mx_hi, fmaxf(s[i][2], s[i][3]));
        }
        mx_lo = fmaxf(mx_lo, __shfl_xor_sync(0xffffffffu, mx_lo, 1));
        mx_lo = fmaxf(mx_lo, __shfl_xor_sync(0xffffffffu, mx_lo, 2));
        mx_hi = fmaxf(mx_hi, __shfl_xor_sync(0xffffffffu, mx_hi, 1));
        mx_hi = fmaxf(mx_hi, __shfl_xor_sync(0xffffffffu, mx_hi, 2));

        const float corr_lo = __expf(m_lo - mx_lo);
        const float corr_hi = __expf(m_hi - mx_hi);
        m_lo = mx_lo; m_hi = mx_hi;
        l_lo *= corr_lo; l_hi *= corr_hi;
#pragma unroll
        for (int i = 0; i < 8; i++) {
            acc[i][0] *= corr_lo; acc[i][1] *= corr_lo;
            acc[i][2] *= corr_hi; acc[i][3] *= corr_hi;
        }

        uint32_t ph[4][4];
#pragma unroll
        for (int t = 0; t < 4; t++) {
#pragma unroll
            for (int half_ = 0; half_ < 2; half_++) {
                const int nt = 2 * t + half_;
                float p0 = __expf(s[nt][0] - mx_lo);
                float p1 = __expf(s[nt][1] - mx_lo);
                float p2 = __expf(s[nt][2] - mx_hi);
                float p3 = __expf(s[nt][3] - mx_hi);
                l_lo += p0 + p1; l_hi += p2 + p3;
                __half2 h01 = __floats2half2_rn(p0, p1);
                __half2 h23 = __floats2half2_rn(p2, p3);
                ph[t][half_ * 2 + 0] = *(uint32_t*)&h01;
                ph[t][half_ * 2 + 1] = *(uint32_t*)&h23;
            }
        }

#pragma unroll
        for (int np = 0; np < 4; np++) {
#pragma unroll
            for (int t = 0; t < 4; t++) {
                uint32_t v0, v1, v2, v3;
                ldm_x4t(v0, v1, v2, v3,
                        vb_ + (t * 16 + lr + l3 * 8) * AT_ROWB + np * 32 + l4 * 16);
                uint32_t b0[2] = {v0, v1}, b1[2] = {v2, v3};
                mma_f16(acc[np * 2 + 0], ph[t], b0);
                mma_f16(acc[np * 2 + 1], ph[t], b1);
            }
        }
    }

    l_lo += __shfl_xor_sync(0xffffffffu, l_lo, 1);
    l_lo += __shfl_xor_sync(0xffffffffu, l_lo, 2);
    l_hi += __shfl_xor_sync(0xffffffffu, l_hi, 1);
    l_hi += __shfl_xor_sync(0xffffffffu, l_hi, 2);
    const float inv_lo = 1.0f / l_lo;
    const float inv_hi = 1.0f / l_hi;

    const int r_lo = q0 + wid * 16 + (lane >> 2);
    const int r_hi = r_lo + 8;
    const size_t base_lo = ((size_t)(b * SEQ + r_lo)) * D_MODEL + h * HEAD_DIM + (lane & 3) * 2;
    const size_t base_hi = ((size_t)(b * SEQ + r_hi)) * D_MODEL + h * HEAD_DIM + (lane & 3) * 2;
#pragma unroll
    for (int nt = 0; nt < 8; nt++) {
        *(__half2*)(Og + base_lo + nt * 8) = __floats2half2_rn(acc[nt][0] * inv_lo, acc[nt][1] * inv_lo);
        *(__half2*)(Og + base_hi + nt * 8) = __floats2half2_rn(acc[nt][2] * inv_hi, acc[nt][3] * inv_hi);
    }
}

// ---------------------------------------------------------------------------
// Wo GEMM: fp16 mma (1 product), BK=64, 2-stage pipeline (round-13 best).
// ---------------------------------------------------------------------------
__global__ __launch_bounds__(256, 2) void gemm_out(
    const __half* __restrict__ Ah, const __half* __restrict__ Wh,
    const float* __restrict__ bias, float* __restrict__ C)
{
    extern __shared__ char dsm[];
    const uint32_t sb = smem_u32(dsm);

    const int tid = threadIdx.x;
    const int wid = tid >> 5;
    const int lane = tid & 31;
    const int wm = wid >> 2;
    const int wn = wid & 3;
    const int bm = blockIdx.y * BM;
    const int bn = blockIdx.x * BN;

    const __half* mats[2] = {Ah, Wh};

    auto load_stage = [&](int sg, int kt) {
        const int kbase = kt * BK;
#pragma unroll
        for (int i = 0; i < 8; i++) {
            int idx = tid + i * 256;
            int mat = idx >> 10;
            int w = idx & 1023;
            int row = w >> 3;
            int c = w & 7;
            int grow = (mat ? bn : bm) + row;
            const __half* gp = mats[mat] + (size_t)grow * D_MODEL + kbase + c * 8;
            uint32_t sa = sb + sg * HSTAGEB + mat * HMATB + row * ROWB + c * 16;
            cp_async16(sa, gp);
        }
    };

    float acc[4][4][4];
#pragma unroll
    for (int a = 0; a < 4; a++)
#pragma unroll
        for (int b2 = 0; b2 < 4; b2++)
#pragma unroll
            for (int q = 0; q < 4; q++) acc[a][b2][q] = 0.f;

    load_stage(0, 0); CP_COMMIT();
    load_stage(1, 1); CP_COMMIT();

    const int lr = lane & 7;
    const int l3 = (lane >> 3) & 1;
    const int l4 = (lane >> 4) & 1;

    const int NK = D_MODEL / BK;
    for (int kt = 0; kt < NK; kt++) {
        const int sg = kt & 1;
        CP_WAIT1();
        __syncthreads();

        const uint32_t abase = sb + sg * HSTAGEB + (wm * 64) * ROWB;
        const uint32_t wbase = sb + sg * HSTAGEB + HMATB + (wn * 32) * ROWB;

#pragma unroll
        for (int ks = 0; ks < 4; ks++) {
            uint32_t af[4][4];
            uint32_t bf_[4][2];
#pragma unroll
            for (int mt = 0; mt < 4; mt++) {
                uint32_t addr = abase + (mt * 16 + lr + l3 * 8) * ROWB + ks * 32 + l4 * 16;
                ldm_x4(af[mt][0], af[mt][1], af[mt][2], af[mt][3], addr);
            }
#pragma unroll
            for (int pr = 0; pr < 2; pr++) {
                uint32_t r0, r1, r2, r3;
                uint32_t addr = wbase + (pr * 16 + lr + l4 * 8) * ROWB + ks * 32 + l3 * 16;
                ldm_x4(r0, r1, r2, r3, addr);
                bf_[pr * 2 + 0][0] = r0;  bf_[pr * 2 + 0][1] = r1;
                bf_[pr * 2 + 1][0] = r2;  bf_[pr * 2 + 1][1] = r3;
            }
#pragma unroll
            for (int mt = 0; mt < 4; mt++)
#pragma unroll
                for (int nt = 0; nt < 4; nt++)
                    mma_f16(acc[mt][nt], af[mt], bf_[nt]);
        }
        __syncthreads();
        if (kt + NSTAGE < NK) load_stage(sg, kt + NSTAGE);
        CP_COMMIT();
    }

    const int qrow = lane >> 2;
    const int qcol = (lane & 3) * 2;
#pragma unroll
    for (int mt = 0; mt < 4; mt++) {
#pragma unroll
        for (int nt = 0; nt < 4; nt++) {
            const int col = bn + wn * 32 + nt * 8 + qcol;
            const float b0 = bias[col], b1 = bias[col + 1];
#pragma unroll
            for (int half_ = 0; half_ < 2; half_++) {
                const int row = bm + wm * 64 + mt * 16 + qrow + half_ * 8;
                float v0 = acc[mt][nt][half_ * 2 + 0] + b0;
                float v1 = acc[mt][nt][half_ * 2 + 1] + b1;
                *(float2*)(C + (size_t)row * D_MODEL + col) = make_float2(v0, v1);
            }
        }
    }
}

// ---------------------------------------------------------------------------
// Launcher
// ---------------------------------------------------------------------------
extern "C" void kernel_launch(void* const* d_in, const int* in_sizes, int n_in,
                              void* d_out, int out_size)
{
    (void)in_sizes; (void)n_in; (void)out_size;
    const float* x  = (const float*)d_in[0];
    const float* Wq = (const float*)d_in[1];
    const float* bq = (const float*)d_in[2];
    const float* Wk = (const float*)d_in[3];
    const float* bk = (const float*)d_in[4];
    const float* Wv = (const float*)d_in[5];
    const float* bv = (const float*)d_in[6];
    const float* Wo = (const float*)d_in[7];
    const float* bo = (const float*)d_in[8];
    const float* gq = (const float*)d_in[9];
    const float* gk = (const float*)d_in[10];
    float* out = (float*)d_out;

    __half *xhlf, *whlf, *wo, *qh, *kh, *vh, *aat;
    uint32_t* bits;
    cudaGetSymbolAddress((void**)&xhlf, g_xhlf);
    cudaGetSymbolAddress((void**)&whlf, g_whlf);
    cudaGetSymbolAddress((void**)&wo, g_wo);
    cudaGetSymbolAddress((void**)&qh, g_qh);
    cudaGetSymbolAddress((void**)&kh, g_kh);
    cudaGetSymbolAddress((void**)&vh, g_vh);
    cudaGetSymbolAddress((void**)&aat, g_aat);
    cudaGetSymbolAddress((void**)&bits, g_flagbits);

    cudaFuncSetAttribute(gemm_hsfn, cudaFuncAttributeMaxDynamicSharedMemorySize, HGEMM_SMEM);
    cudaFuncSetAttribute(gemm_out, cudaFuncAttributeMaxDynamicSharedMemorySize, HGEMM_SMEM);
    cudaFuncSetAttribute(flash_mma, cudaFuncAttributeMaxDynamicSharedMemorySize, FA_SMEM);

    const int nx4 = MTOT * D_MODEL / 4;
    const int nw4 = DD / 4;
    const int ntot = nx4 + 4 * nw4;

    conv_all<<<(ntot + 255) / 256, 256>>>((const float4*)x, (const float4*)Wq,
                                          (const float4*)Wk, (const float4*)Wv,
                                          (const float4*)Wo, (uint2*)xhlf,
                                          (uint2*)whlf, (uint2*)wo, bits, nx4, nw4);

    {
        dim3 ggrid(D_MODEL / BN, MTOT / BM, 3);
        gemm_hsfn<<<ggrid, 256, HGEMM_SMEM>>>(xhlf, whlf, bq, bk, bv, qh, kh, vh, bits);
    }

    fixup_kernel<<<4096, 256>>>(x, Wq, Wk, Wv, bq, bk, bv, qh, kh, vh, bits);

    {
        dim3 nb(32, 8);
        int nrows = MTOT * NHEAD;               // 65536
        qknorm_h<<<nrows / 8, nb>>>((__half2*)qh, (__half2*)kh, gq, gk);
    }

    {
        dim3 fgrid(SEQ / 128, BATCH * NHEAD);
        flash_mma<<<fgrid, 256, FA_SMEM>>>(qh, kh, vh, aat);
    }

    {
        dim3 mgrid(D_MODEL / BN, MTOT / BM);
        gemm_out<<<mgrid, 256, HGEMM_SMEM>>>(aat, wo, bo, out);
    }
}

// round 16
// speedup vs baseline: 1.2783x; 1.0066x over previous
#include <cuda_runtime.h>
#include <cuda_bf16.h>
#include <cuda_fp16.h>
#include <math.h>
#include <stdint.h>

#define D_MODEL 1024
#define NHEAD 16
#define HEAD_DIM 64
#define BATCH 2
#define SEQ 2048
#define MTOT (BATCH * SEQ) /* 4096 */
#define DD (D_MODEL * D_MODEL)
#define NBITS_WORDS (3 * MTOT * D_MODEL / 32)   /* 393216 */

// ---------------------------------------------------------------------------
// Scratch (device globals — no allocation allowed anywhere)
// ---------------------------------------------------------------------------
__device__ __half g_xhlf[MTOT * D_MODEL];
__device__ __half g_whlf[3 * DD];
__device__ __half g_wo[DD];
__device__ __half g_qh[MTOT * D_MODEL];
__device__ __half g_kh[MTOT * D_MODEL];
__device__ __half g_vh[MTOT * D_MODEL];
__device__ __half g_aat[MTOT * D_MODEL];
__device__ uint32_t g_flagbits[NBITS_WORDS];

// ---------------------------------------------------------------------------
// helpers
// ---------------------------------------------------------------------------
__device__ __forceinline__ uint32_t smem_u32(const void* p) {
    uint32_t a;
    asm("{ .reg .u64 t; cvta.to.shared.u64 t, %1; cvt.u32.u64 %0, t; }" : "=r"(a) : "l"(p));
    return a;
}
__device__ __forceinline__ void cp_async16(uint32_t sa, const void* ga) {
    asm volatile("cp.async.cg.shared.global [%0], [%1], 16;" :: "r"(sa), "l"(ga) : "memory");
}
#define CP_COMMIT() asm volatile("cp.async.commit_group;" ::: "memory")
#define CP_WAIT1()  asm volatile("cp.async.wait_group 1;" ::: "memory")
#define CP_WAIT2()  asm volatile("cp.async.wait_group 2;" ::: "memory")

__device__ __forceinline__ void ldm_x4(uint32_t& r0, uint32_t& r1, uint32_t& r2, uint32_t& r3,
                                       uint32_t addr) {
    asm volatile("ldmatrix.sync.aligned.m8n8.x4.shared.b16 {%0,%1,%2,%3}, [%4];"
                 : "=r"(r0), "=r"(r1), "=r"(r2), "=r"(r3) : "r"(addr));
}
__device__ __forceinline__ void ldm_x4t(uint32_t& r0, uint32_t& r1, uint32_t& r2, uint32_t& r3,
                                        uint32_t addr) {
    asm volatile("ldmatrix.sync.aligned.m8n8.x4.trans.shared.b16 {%0,%1,%2,%3}, [%4];"
                 : "=r"(r0), "=r"(r1), "=r"(r2), "=r"(r3) : "r"(addr));
}
__device__ __forceinline__ void mma_f16(float* c, const uint32_t* a, const uint32_t* b) {
    asm volatile(
        "mma.sync.aligned.m16n8k16.row.col.f32.f16.f16.f32 "
        "{%0,%1,%2,%3}, {%4,%5,%6,%7}, {%8,%9}, {%0,%1,%2,%3};"
        : "+f"(c[0]), "+f"(c[1]), "+f"(c[2]), "+f"(c[3])
        : "r"(a[0]), "r"(a[1]), "r"(a[2]), "r"(a[3]), "r"(b[0]), "r"(b[1]));
}

// ---------------------------------------------------------------------------
// small kernels
// ---------------------------------------------------------------------------
__device__ __forceinline__ uint2 cvt_quad(float4 x) {
    __half2 a = __floats2half2_rn(x.x, x.y);
    __half2 b = __floats2half2_rn(x.z, x.w);
    uint2 o;
    o.x = *(uint32_t*)&a;
    o.y = *(uint32_t*)&b;
    return o;
}

__global__ void conv_all(const float4* __restrict__ x,
                         const float4* __restrict__ wq, const float4* __restrict__ wk,
                         const float4* __restrict__ wv, const float4* __restrict__ wo,
                         uint2* __restrict__ xh, uint2* __restrict__ whlf,
                         uint2* __restrict__ woh, uint32_t* __restrict__ bits,
                         int nx4, int nw4)
{
    int i = blockIdx.x * blockDim.x + threadIdx.x;
    if (i < NBITS_WORDS) bits[i] = 0;
    if (i < nx4) { xh[i] = cvt_quad(x[i]); return; }
    i -= nx4;
    if (i < nw4) { whlf[i] = cvt_quad(wq[i]); return; }
    i -= nw4;
    if (i < nw4) { whlf[nw4 + i] = cvt_quad(wk[i]); return; }
    i -= nw4;
    if (i < nw4) { whlf[2 * nw4 + i] = cvt_quad(wv[i]); return; }
    i -= nw4;
    if (i < nw4) woh[i] = cvt_quad(wo[i]);
}

// ---------------------------------------------------------------------------
// qk-norm on fp16, in place: Q <- (Q/rms)*gq*0.125, K <- (K/rms)*gk
// ---------------------------------------------------------------------------
__global__ void qknorm_h(__half2* __restrict__ Q, __half2* __restrict__ K,
                         const float* __restrict__ gq, const float* __restrict__ gk)
{
    const int row = blockIdx.x * blockDim.y + threadIdx.y;
    const int lane = threadIdx.x;

    __half2* qb = Q + (size_t)row * 32;
    __half2* kb = K + (size_t)row * 32;

    float2 xq = __half22float2(qb[lane]);
    float2 xk = __half22float2(kb[lane]);

    float sq = xq.x * xq.x + xq.y * xq.y;
    float sk = xk.x * xk.x + xk.y * xk.y;
#pragma unroll
    for (int o = 16; o; o >>= 1) {
        sq += __shfl_xor_sync(0xffffffffu, sq, o);
        sk += __shfl_xor_sync(0xffffffffu, sk, o);
    }
    const float invq = rsqrtf(sq * (1.0f / 64.0f) + 1e-6f) * 0.125f;
    const float invk = rsqrtf(sk * (1.0f / 64.0f) + 1e-6f);

    const float gq0 = __ldg(gq + lane * 2), gq1 = __ldg(gq + lane * 2 + 1);
    const float gk0 = __ldg(gk + lane * 2), gk1 = __ldg(gk + lane * 2 + 1);

    qb[lane] = __floats2half2_rn(xq.x * invq * gq0, xq.y * invq * gq1);
    kb[lane] = __floats2half2_rn(xk.x * invk * gk0, xk.y * invk * gk1);
}

// ---------------------------------------------------------------------------
// QKV GEMM: fp16 mma (1 product), BK=64, 3-stage EARLY-ISSUE pipeline.
// ---------------------------------------------------------------------------
#define BM 128
#define BN 128
#define BK 64
#define ROWB 144
#define HMATB (128 * ROWB)              /* 18432 */
#define HSTAGEB (2 * HMATB)             /* 36864 */
#define NSTAGE 3
#define HGEMM_SMEM (NSTAGE * HSTAGEB)   /* 110592 -> 2 blocks/SM on 228KB */
#define SFN_THR 4.0e-3f

__global__ __launch_bounds__(256, 2) void gemm_hsfn(
    const __half* __restrict__ Ah, const __half* __restrict__ WhB,
    const float* __restrict__ bq, const float* __restrict__ bk, const float* __restrict__ bv,
    __half* __restrict__ Cq, __half* __restrict__ Ck, __half* __restrict__ Cv,
    uint32_t* __restrict__ bits)
{
    extern __shared__ char dsm[];
    const uint32_t sb = smem_u32(dsm);

    const int z = blockIdx.z;
    const __half* Wh = WhB + (size_t)z * DD;
    const float* bias = (z == 0) ? bq : (z == 1) ? bk : bv;
    __half* C = (z == 0) ? Cq : (z == 1) ? Ck : Cv;

    const int tid = threadIdx.x;
    const int wid = tid >> 5;
    const int lane = tid & 31;
    const int wm = wid >> 2;
    const int wn = wid & 3;
    const int bm = blockIdx.y * BM;
    const int bn = blockIdx.x * BN;

    const __half* mats[2] = {Ah, Wh};

    auto load_stage = [&](int sg, int kt) {
        const int kbase = kt * BK;
#pragma unroll
        for (int i = 0; i < 8; i++) {
            int idx = tid + i * 256;
            int mat = idx >> 10;
            int w = idx & 1023;
            int row = w >> 3;
            int c = w & 7;
            int grow = (mat ? bn : bm) + row;
            const __half* gp = mats[mat] + (size_t)grow * D_MODEL + kbase + c * 8;
            uint32_t sa = sb + sg * HSTAGEB + mat * HMATB + row * ROWB + c * 16;
            cp_async16(sa, gp);
        }
    };

    float acc[4][4][4];
#pragma unroll
    for (int a = 0; a < 4; a++)
#pragma unroll
        for (int b2 = 0; b2 < 4; b2++)
#pragma unroll
            for (int q = 0; q < 4; q++) acc[a][b2][q] = 0.f;

    load_stage(0, 0); CP_COMMIT();
    load_stage(1, 1); CP_COMMIT();

    const int lr = lane & 7;
    const int l3 = (lane >> 3) & 1;
    const int l4 = (lane >> 4) & 1;

    int sg = 0;                         // compute stage index (kt mod 3)
    int sl = 2;                         // load stage index ((kt+2) mod 3)
    const int NK = D_MODEL / BK;        // 16
    for (int kt = 0; kt < NK; kt++) {
        CP_WAIT1();                     // stage kt resident (<=1 pending group)
        __syncthreads();                // all warps done reading stage kt-1

        // EARLY: issue kt+2 into the stage freed at kt-1, before compute
        if (kt + 2 < NK) load_stage(sl, kt + 2);
        CP_COMMIT();

        const uint32_t abase = sb + sg * HSTAGEB + (wm * 64) * ROWB;
        const uint32_t wbase = sb + sg * HSTAGEB + HMATB + (wn * 32) * ROWB;

#pragma unroll
        for (int ks = 0; ks < 4; ks++) {
            uint32_t af[4][4];
            uint32_t bf_[4][2];
#pragma unroll
            for (int mt = 0; mt < 4; mt++) {
                uint32_t addr = abase + (mt * 16 + lr + l3 * 8) * ROWB + ks * 32 + l4 * 16;
                ldm_x4(af[mt][0], af[mt][1], af[mt][2], af[mt][3], addr);
            }
#pragma unroll
            for (int pr = 0; pr < 2; pr++) {
                uint32_t r0, r1, r2, r3;
                uint32_t addr = wbase + (pr * 16 + lr + l4 * 8) * ROWB + ks * 32 + l3 * 16;
                ldm_x4(r0, r1, r2, r3, addr);
                bf_[pr * 2 + 0][0] = r0;  bf_[pr * 2 + 0][1] = r1;
                bf_[pr * 2 + 1][0] = r2;  bf_[pr * 2 + 1][1] = r3;
            }
#pragma unroll
            for (int mt = 0; mt < 4; mt++)
#pragma unroll
                for (int nt = 0; nt < 4; nt++)
                    mma_f16(acc[mt][nt], af[mt], bf_[nt]);
        }
        sg = (sg == 2) ? 0 : sg + 1;
        sl = (sl == 2) ? 0 : sl + 1;
    }

    const int qrow = lane >> 2;
    const int qcol = (lane & 3) * 2;
    const size_t zbase = (size_t)z * MTOT * D_MODEL;
#pragma unroll
    for (int mt = 0; mt < 4; mt++) {
#pragma unroll
        for (int nt = 0; nt < 4; nt++) {
            const int col = bn + wn * 32 + nt * 8 + qcol;
            const float b0 = bias[col], b1 = bias[col + 1];
#pragma unroll
            for (int half_ = 0; half_ < 2; half_++) {
                const int row = bm + wm * 64 + mt * 16 + qrow + half_ * 8;
                float v0 = acc[mt][nt][half_ * 2 + 0] + b0;
                float v1 = acc[mt][nt][half_ * 2 + 1] + b1;
                float t0 = v0 * 2.0f, t1 = v1 * 2.0f;
                float r0 = rintf(t0), r1 = rintf(t1);
                if (fabsf(t0 - r0) > 0.5f - SFN_THR) {
                    size_t g = zbase + (size_t)row * D_MODEL + col;
                    atomicOr(&bits[g >> 5], 1u << (g & 31));
                }
                if (fabsf(t1 - r1) > 0.5f - SFN_THR) {
                    size_t g = zbase + (size_t)row * D_MODEL + col + 1;
                    atomicOr(&bits[g >> 5], 1u << (g & 31));
                }
                r0 = fminf(8.f, fmaxf(-8.f, r0));
                r1 = fminf(8.f, fmaxf(-8.f, r1));
                __half2 o = __floats2half2_rn(r0 * 0.5f, r1 * 0.5f);
                *(__half2*)(C + (size_t)row * D_MODEL + col) = o;
            }
        }
    }
}

// ---------------------------------------------------------------------------
// Fix-up: recompute flagged elements with fp32 dot (warp per element)
// ---------------------------------------------------------------------------
__global__ __launch_bounds__(256) void fixup_kernel(
    const float* __restrict__ x,
    const float* __restrict__ Wq, const float* __restrict__ Wk, const float* __restrict__ Wv,
    const float* __restrict__ bq, const float* __restrict__ bk, const float* __restrict__ bv,
    __half* __restrict__ Q, __half* __restrict__ K, __half* __restrict__ V,
    const uint32_t* __restrict__ bits)
{
    const int warp = (blockIdx.x * blockDim.x + threadIdx.x) >> 5;
    const int lane = threadIdx.x & 31;
    const int nw = (gridDim.x * blockDim.x) >> 5;

    for (int w = warp; w < NBITS_WORDS; w += nw) {
        uint32_t word = bits[w];
        while (word) {
            int bit = __ffs(word) - 1;
            word &= word - 1;
            size_t g = ((size_t)w << 5) + bit;
            int z = (int)(g / ((size_t)MTOT * D_MODEL));
            size_t rem = g - (size_t)z * MTOT * D_MODEL;
            int row = (int)(rem >> 10);
            int col = (int)(rem & 1023);
            const float* W = (z == 0) ? Wq : (z == 1) ? Wk : Wv;
            const float* bias = (z == 0) ? bq : (z == 1) ? bk : bv;
            __half* C = (z == 0) ? Q : (z == 1) ? K : V;

            const float* xr = x + (size_t)row * D_MODEL;
            const float* wr = W + (size_t)col * D_MODEL;
            float4 av[8], bv_[8];
#pragma unroll
            for (int u = 0; u < 8; u++) {
                av[u]  = *(const float4*)(xr + lane * 4 + u * 128);
                bv_[u] = *(const float4*)(wr + lane * 4 + u * 128);
            }
            float s = 0.f;
#pragma unroll
            for (int u = 0; u < 8; u++) {
                s = fmaf(av[u].x, bv_[u].x, s); s = fmaf(av[u].y, bv_[u].y, s);
                s = fmaf(av[u].z, bv_[u].z, s); s = fmaf(av[u].w, bv_[u].w, s);
            }
#pragma unroll
            for (int o = 16; o; o >>= 1) s += __shfl_xor_sync(0xffffffffu, s, o);
            if (lane == 0) {
                float c = s + bias[col];
                float r = fminf(8.f, fmaxf(-8.f, rintf(c * 2.f)));
                C[(size_t)row * D_MODEL + col] = __float2half(r * 0.5f);
            }
        }
    }
}

// ---------------------------------------------------------------------------
// Flash attention v2 (round-15 proven): pre-normalized fp16 inputs,
// K/V via 4-stage early-issue cp.async, Q staged once.
// ---------------------------------------------------------------------------
#define AT_ROWB 144
#define KMATB (64 * AT_ROWB)            /* 9216 */
#define KVSTG (2 * KMATB)               /* 18432 per stage */
#define FA_NST 4
#define FA_SMEM (128 * AT_ROWB + FA_NST * KVSTG)  /* 92160 */

__global__ __launch_bounds__(256) void flash_mma(
    const __half* __restrict__ Qg, const __half* __restrict__ Kg,
    const __half* __restrict__ Vg, __half* __restrict__ Og)
{
    extern __shared__ char smp[];
    const uint32_t sb = smem_u32(smp);
    const uint32_t oKV = 128 * AT_ROWB;

    const int tid = threadIdx.x, wid = tid >> 5, lane = tid & 31;
    const int b = blockIdx.y >> 4, h = blockIdx.y & 15;
    const int q0 = blockIdx.x * 128;

    const int lr = lane & 7, l3 = (lane >> 3) & 1, l4 = (lane >> 4) & 1;

    auto load_q = [&]() {
#pragma unroll
        for (int i = 0; i < 4; i++) {
            int idx = tid + i * 256;
            int row = idx >> 3, c = idx & 7;
            const __half* gp = Qg + ((size_t)(b * SEQ + q0 + row)) * D_MODEL + h * HEAD_DIM + c * 8;
            cp_async16(sb + row * AT_ROWB + c * 16, gp);
        }
    };
    auto load_kv = [&](int sg, int kt) {
#pragma unroll
        for (int i = 0; i < 4; i++) {
            int idx = tid + i * 256;
            int mat = idx >> 9;
            int w = idx & 511;
            int row = w >> 3, c = w & 7;
            const __half* gp = (mat ? Vg : Kg) +
                ((size_t)(b * SEQ + kt * 64 + row)) * D_MODEL + h * HEAD_DIM + c * 8;
            cp_async16(sb + oKV + sg * KVSTG + mat * KMATB + row * AT_ROWB + c * 16, gp);
        }
    };

    load_q(); load_kv(0, 0); CP_COMMIT();
    load_kv(1, 1); CP_COMMIT();
    load_kv(2, 2); CP_COMMIT();

    CP_WAIT2();
    __syncthreads();

    uint32_t qf[4][4];
    {
        const int rbase = wid * 16 + lr + l3 * 8;
#pragma unroll
        for (int ks = 0; ks < 4; ks++)
            ldm_x4(qf[ks][0], qf[ks][1], qf[ks][2], qf[ks][3],
                   sb + rbase * AT_ROWB + ks * 32 + l4 * 16);
    }

    float m_lo = -INFINITY, m_hi = -INFINITY, l_lo = 0.f, l_hi = 0.f;
    float acc[8][4];
#pragma unroll
    for (int i = 0; i < 8; i++)
#pragma unroll
        for (int j = 0; j < 4; j++) acc[i][j] = 0.f;

    const int NT = SEQ / 64;
    for (int kt = 0; kt < NT; kt++) {
        if (kt > 0) {
            CP_WAIT2();
            __syncthreads();
        }
        if (kt + 3 < NT) load_kv((kt + 3) & (FA_NST - 1), kt + 3);
        CP_COMMIT();

        const uint32_t kb_ = sb + oKV + (kt & (FA_NST - 1)) * KVSTG;
        const uint32_t vb_ = kb_ + KMATB;

        float s[8][4];
#pragma unroll
        for (int i = 0; i < 8; i++)
#pragma unroll
            for (int j = 0; j < 4; j++) s[i][j] = 0.f;

#pragma unroll
        for (int np = 0; np < 4; np++) {
            const int rb = np * 16 + lr + l4 * 8;
#pragma unroll
            for (int ks = 0; ks < 4; ks++) {
                uint32_t k0, k1, k2, k3;
                ldm_x4(k0, k1, k2, k3, kb_ + rb * AT_ROWB + ks * 32 + l3 * 16);
                uint32_t b0[2] = {k0, k1}, b1[2] = {k2, k3};
                mma_f16(s[np * 2 + 0], qf[ks], b0);
                mma_f16(s[np * 2 + 1], qf[ks], b1);
            }
        }

        float mx_lo = m_lo, mx_hi = m_hi;
#pragma unroll
        for (int i = 0; i < 8; i++) {
            mx_lo = fmaxf(mx_lo, fmaxf(s[i][0], s[i][1]));
            mx_hi = fmaxf(mx_hi, fmaxf(s[i][2], s[i][3]));
        }
        mx_lo = fmaxf(mx_lo, __shfl_xor_sync(0xffffffffu, mx_lo, 1));
        mx_lo = fmaxf(mx_lo, __shfl_xor_sync(0xffffffffu, mx_lo, 2));
        mx_hi = fmaxf(mx_hi, __shfl_xor_sync(0xffffffffu, mx_hi, 1));
        mx_hi = fmaxf(mx_hi, __shfl_xor_sync(0xffffffffu, mx_hi, 2));

        const float corr_lo = __expf(m_lo - mx_lo);
        const float corr_hi = __expf(m_hi - mx_hi);
        m_lo = mx_lo; m_hi = mx_hi;
        l_lo *= corr_lo; l_hi *= corr_hi;
#pragma unroll
        for (int i = 0; i < 8; i++) {
            acc[i][0] *= corr_lo; acc[i][1] *= corr_lo;
            acc[i][2] *= corr_hi; acc[i][3] *= corr_hi;
        }

        uint32_t ph[4][4];
#pragma unroll
        for (int t = 0; t < 4; t++) {
#pragma unroll
            for (int half_ = 0; half_ < 2; half_++) {
                const int nt = 2 * t + half_;
                float p0 = __expf(s[nt][0] - mx_lo);
                float p1 = __expf(s[nt][1] - mx_lo);
                float p2 = __expf(s[nt][2] - mx_hi);
                float p3 = __expf(s[nt][3] - mx_hi);
                l_lo += p0 + p1; l_hi += p2 + p3;
                __half2 h01 = __floats2half2_rn(p0, p1);
                __half2 h23 = __floats2half2_rn(p2, p3);
                ph[t][half_ * 2 + 0] = *(uint32_t*)&h01;
                ph[t][half_ * 2 + 1] = *(uint32_t*)&h23;
            }
        }

#pragma unroll
        for (int np = 0; np < 4; np++) {
#pragma unroll
            for (int t = 0; t < 4; t++) {
                uint32_t v0, v1, v2, v3;
                ldm_x4t(v0, v1, v2, v3,
                        vb_ + (t * 16 + lr + l3 * 8) * AT_ROWB + np * 32 + l4 * 16);
                uint32_t b0[2] = {v0, v1}, b1[2] = {v2, v3};
                mma_f16(acc[np * 2 + 0], ph[t], b0);
                mma_f16(acc[np * 2 + 1], ph[t], b1);
            }
        }
    }

    l_lo += __shfl_xor_sync(0xffffffffu, l_lo, 1);
    l_lo += __shfl_xor_sync(0xffffffffu, l_lo, 2);
    l_hi += __shfl_xor_sync(0xffffffffu, l_hi, 1);
    l_hi += __shfl_xor_sync(0xffffffffu, l_hi, 2);
    const float inv_lo = 1.0f / l_lo;
    const float inv_hi = 1.0f / l_hi;

    const int r_lo = q0 + wid * 16 + (lane >> 2);
    const int r_hi = r_lo + 8;
    const size_t base_lo = ((size_t)(b * SEQ + r_lo)) * D_MODEL + h * HEAD_DIM + (lane & 3) * 2;
    const size_t base_hi = ((size_t)(b * SEQ + r_hi)) * D_MODEL + h * HEAD_DIM + (lane & 3) * 2;
#pragma unroll
    for (int nt = 0; nt < 8; nt++) {
        *(__half2*)(Og + base_lo + nt * 8) = __floats2half2_rn(acc[nt][0] * inv_lo, acc[nt][1] * inv_lo);
        *(__half2*)(Og + base_hi + nt * 8) = __floats2half2_rn(acc[nt][2] * inv_hi, acc[nt][3] * inv_hi);
    }
}

// ---------------------------------------------------------------------------
// Wo GEMM: fp16 mma (1 product), BK=64, 3-stage early-issue pipeline.
// ---------------------------------------------------------------------------
__global__ __launch_bounds__(256, 2) void gemm_out(
    const __half* __restrict__ Ah, const __half* __restrict__ Wh,
    const float* __restrict__ bias, float* __restrict__ C)
{
    extern __shared__ char dsm[];
    const uint32_t sb = smem_u32(dsm);

    const int tid = threadIdx.x;
    const int wid = tid >> 5;
    const int lane = tid & 31;
    const int wm = wid >> 2;
    const int wn = wid & 3;
    const int bm = blockIdx.y * BM;
    const int bn = blockIdx.x * BN;

    const __half* mats[2] = {Ah, Wh};

    auto load_stage = [&](int sg, int kt) {
        const int kbase = kt * BK;
#pragma unroll
        for (int i = 0; i < 8; i++) {
            int idx = tid + i * 256;
            int mat = idx >> 10;
            int w = idx & 1023;
            int row = w >> 3;
            int c = w & 7;
            int grow = (mat ? bn : bm) + row;
            const __half* gp = mats[mat] + (size_t)grow * D_MODEL + kbase + c * 8;
            uint32_t sa = sb + sg * HSTAGEB + mat * HMATB + row * ROWB + c * 16;
            cp_async16(sa, gp);
        }
    };

    float acc[4][4][4];
#pragma unroll
    for (int a = 0; a < 4; a++)
#pragma unroll
        for (int b2 = 0; b2 < 4; b2++)
#pragma unroll
            for (int q = 0; q < 4; q++) acc[a][b2][q] = 0.f;

    load_stage(0, 0); CP_COMMIT();
    load_stage(1, 1); CP_COMMIT();

    const int lr = lane & 7;
    const int l3 = (lane >> 3) & 1;
    const int l4 = (lane >> 4) & 1;

    int sg = 0, sl = 2;
    const int NK = D_MODEL / BK;
    for (int kt = 0; kt < NK; kt++) {
        CP_WAIT1();
        __syncthreads();

        if (kt + 2 < NK) load_stage(sl, kt + 2);
        CP_COMMIT();

        const uint32_t abase = sb + sg * HSTAGEB + (wm * 64) * ROWB;
        const uint32_t wbase = sb + sg * HSTAGEB + HMATB + (wn * 32) * ROWB;

#pragma unroll
        for (int ks = 0; ks < 4; ks++) {
            uint32_t af[4][4];
            uint32_t bf_[4][2];
#pragma unroll
            for (int mt = 0; mt < 4; mt++) {
                uint32_t addr = abase + (mt * 16 + lr + l3 * 8) * ROWB + ks * 32 + l4 * 16;
                ldm_x4(af[mt][0], af[mt][1], af[mt][2], af[mt][3], addr);
            }
#pragma unroll
            for (int pr = 0; pr < 2; pr++) {
                uint32_t r0, r1, r2, r3;
                uint32_t addr = wbase + (pr * 16 + lr + l4 * 8) * ROWB + ks * 32 + l3 * 16;
                ldm_x4(r0, r1, r2, r3, addr);
                bf_[pr * 2 + 0][0] = r0;  bf_[pr * 2 + 0][1] = r1;
                bf_[pr * 2 + 1][0] = r2;  bf_[pr * 2 + 1][1] = r3;
            }
#pragma unroll
            for (int mt = 0; mt < 4; mt++)
#pragma unroll
                for (int nt = 0; nt < 4; nt++)
                    mma_f16(acc[mt][nt], af[mt], bf_[nt]);
        }
        sg = (sg == 2) ? 0 : sg + 1;
        sl = (sl == 2) ? 0 : sl + 1;
    }

    const int qrow = lane >> 2;
    const int qcol = (lane & 3) * 2;
#pragma unroll
    for (int mt = 0; mt < 4; mt++) {
#pragma unroll
        for (int nt = 0; nt < 4; nt++) {
            const int col = bn + wn * 32 + nt * 8 + qcol;
            const float b0 = bias[col], b1 = bias[col + 1];
#pragma unroll
            for (int half_ = 0; half_ < 2; half_++) {
                const int row = bm + wm * 64 + mt * 16 + qrow + half_ * 8;
                float v0 = acc[mt][nt][half_ * 2 + 0] + b0;
                float v1 = acc[mt][nt][half_ * 2 + 1] + b1;
                *(float2*)(C + (size_t)row * D_MODEL + col) = make_float2(v0, v1);
            }
        }
    }
}

// ---------------------------------------------------------------------------
// Launcher
// ---------------------------------------------------------------------------
extern "C" void kernel_launch(void* const* d_in, const int* in_sizes, int n_in,
                              void* d_out, int out_size)
{
    (void)in_sizes; (void)n_in; (void)out_size;
    const float* x  = (const float*)d_in[0];
    const float* Wq = (const float*)d_in[1];
    const float* bq = (const float*)d_in[2];
    const float* Wk = (const float*)d_in[3];
    const float* bk = (const float*)d_in[4];
    const float* Wv = (const float*)d_in[5];
    const float* bv = (const float*)d_in[6];
    const float* Wo = (const float*)d_in[7];
    const float* bo = (const float*)d_in[8];
    const float* gq = (const float*)d_in[9];
    const float* gk = (const float*)d_in[10];
    float* out = (float*)d_out;

    __half *xhlf, *whlf, *wo, *qh, *kh, *vh, *aat;
    uint32_t* bits;
    cudaGetSymbolAddress((void**)&xhlf, g_xhlf);
    cudaGetSymbolAddress((void**)&whlf, g_whlf);
    cudaGetSymbolAddress((void**)&wo, g_wo);
    cudaGetSymbolAddress((void**)&qh, g_qh);
    cudaGetSymbolAddress((void**)&kh, g_kh);
    cudaGetSymbolAddress((void**)&vh, g_vh);
    cudaGetSymbolAddress((void**)&aat, g_aat);
    cudaGetSymbolAddress((void**)&bits, g_flagbits);

    cudaFuncSetAttribute(gemm_hsfn, cudaFuncAttributeMaxDynamicSharedMemorySize, HGEMM_SMEM);
    cudaFuncSetAttribute(gemm_out, cudaFuncAttributeMaxDynamicSharedMemorySize, HGEMM_SMEM);
    cudaFuncSetAttribute(flash_mma, cudaFuncAttributeMaxDynamicSharedMemorySize, FA_SMEM);

    const int nx4 = MTOT * D_MODEL / 4;
    const int nw4 = DD / 4;
    const int ntot = nx4 + 4 * nw4;

    conv_all<<<(ntot + 255) / 256, 256>>>((const float4*)x, (const float4*)Wq,
                                          (const float4*)Wk, (const float4*)Wv,
                                          (const float4*)Wo, (uint2*)xhlf,
                                          (uint2*)whlf, (uint2*)wo, bits, nx4, nw4);

    {
        dim3 ggrid(D_MODEL / BN, MTOT / BM, 3);
        gemm_hsfn<<<ggrid, 256, HGEMM_SMEM>>>(xhlf, whlf, bq, bk, bv, qh, kh, vh, bits);
    }

    fixup_kernel<<<4096, 256>>>(x, Wq, Wk, Wv, bq, bk, bv, qh, kh, vh, bits);

    {
        dim3 nb(32, 8);
        int nrows = MTOT * NHEAD;
        qknorm_h<<<nrows / 8, nb>>>((__half2*)qh, (__half2*)kh, gq, gk);
    }

    {
        dim3 fgrid(SEQ / 128, BATCH * NHEAD);
        flash_mma<<<fgrid, 256, FA_SMEM>>>(qh, kh, vh, aat);
    }

    {
        dim3 mgrid(D_MODEL / BN, MTOT / BM);
        gemm_out<<<mgrid, 256, HGEMM_SMEM>>>(aat, wo, bo, out);
    }
}